// round 8
// baseline (speedup 1.0000x reference)
#include <cuda_runtime.h>
#include <stdint.h>

// Binarized depthwise 3x3 conv, stride 1, SAME. x:(16,112,112,256) NHWC fp32,
// kernel:(3,3,256,1). out = sum of sign(x)*sign(k) over valid taps.
//
// bf16x2 math: pack 2 channels' fp32 high-halves into one reg (PRMT); per tap
// one LOP3 ((t & 0x80008000) ^ kp) yields bf16x2 of +-1.0 (or +-0.0 when kp
// is zeroed for a missing border row); accumulate with add.rn.bf16x2 (exact,
// |sum| <= 9). Streaming column recurrence per output row:
//   out[c-1] = A + q2(c); A = B + q1(c); B = q0(c)
//
// QUAD-ROW grouping: 4 output rows per thread from 6 input rows -> input
// passes through L2 1.5x (R7's 2x row-pairing computed to 9.1 TB/s L2, ~80%
// of the 11.3 TB/s LTS cap; this drops it to ~7.6). Middle rows load at
// constant immediate offsets (RS..3RS) from one base pointer.

#define NN 16
#define HH 112
#define WW 112
#define CC 256
#define RS (WW * CC)            // row stride in elements

__device__ __forceinline__ uint32_t badd(uint32_t a, uint32_t b) {
    uint32_t r;
    asm("add.rn.bf16x2 %0, %1, %2;" : "=r"(r) : "r"(a), "r"(b));
    return r;
}

#define TAPP(t, kp) ((((t) & 0x80008000u)) ^ (kp))

__device__ __forceinline__ uint32_t pack2(const float* __restrict__ p) {
    const float2 v = *reinterpret_cast<const float2*>(p);
    return __byte_perm(__float_as_uint(v.x), __float_as_uint(v.y), 0x7632);
}

__device__ __forceinline__ void store2(float* __restrict__ p, uint32_t ov) {
    float2 o2;
    o2.x = __uint_as_float(ov << 16);
    o2.y = __uint_as_float(ov & 0xFFFF0000u);
    *reinterpret_cast<float2*>(p) = o2;
}

__global__ __launch_bounds__(128, 8)
void bconv_kernel(const float* __restrict__ x,
                  const float* __restrict__ k,
                  float* __restrict__ out) {
    const int quad = blockIdx.x >> 2;       // 0..27 -> output rows 4q..4q+3
    const int strip = blockIdx.x & 3;       // 4 strips of 28 columns
    const int n = blockIdx.y;
    const int t = threadIdx.x;              // channel pair 0..127
    const int c0 = t * 2;

    const int h0 = quad * 4;
    const bool hasT = (quad != 0);          // row h0-1 exists
    const bool hasB = (quad != 27);         // row h0+4 exists

    // Kernel signs as bf16x2 of +-1.0 per channel pair.
    uint32_t kp[3][3];
#pragma unroll
    for (int kh = 0; kh < 3; ++kh)
#pragma unroll
        for (int kw = 0; kw < 3; ++kw) {
            const float2 kv = *reinterpret_cast<const float2*>(k + (kh * 3 + kw) * CC + c0);
            uint32_t s0 = (kv.x >= 0.0f) ? 0x3F80u : 0xBF80u;
            uint32_t s1 = (kv.y >= 0.0f) ? 0x3F80u : 0xBF80u;
            kp[kh][kw] = s0 | (s1 << 16);
        }
    // Border-zeroed outer taps (zeroed kp adds +-0.0 -> no-op).
    uint32_t kpA0[3], kpD2[3];
#pragma unroll
    for (int kw = 0; kw < 3; ++kw) {
        kpA0[kw] = hasT ? kp[0][kw] : 0u;
        kpD2[kw] = hasB ? kp[2][kw] : 0u;
    }

    // r1 = row h0. Rows h0+1..h0+3 are r1 + RS/2RS/3RS (constant offsets).
    // r0 (h0-1) and r5 (h0+4) clamp to valid rows when absent (zeroed via kp).
    const float* r1 = x + (((size_t)n * HH + h0) * WW) * CC + c0;
    const float* r0 = hasT ? r1 - RS : r1;
    const float* r5 = hasB ? r1 + 4 * RS : r1;
    float*       oA = out + (((size_t)n * HH + h0) * WW) * CC + c0;

    const int ws = strip * (WW / 4);
    const int we = ws + (WW / 4);
    const int cbeg = (ws == 0) ? 0 : ws - 1;
    const int cend = (we == WW) ? WW - 1 : we;

    uint32_t AA, BA, AB, BB, AC, BC, AD, BD;

    // ---- peeled first column (no store) ----
    {
        const size_t cc = (size_t)cbeg * CC;
        const uint32_t t0 = pack2(r0 + cc);
        const uint32_t t1 = pack2(r1 + cc);
        const uint32_t t2 = pack2(r1 + cc + RS);
        const uint32_t t3 = pack2(r1 + cc + 2 * RS);
        const uint32_t t4 = pack2(r1 + cc + 3 * RS);
        const uint32_t t5 = pack2(r5 + cc);
        BA = badd(badd(TAPP(t0, kpA0[0]), TAPP(t1, kp[1][0])), TAPP(t2, kp[2][0]));
        AA = badd(badd(TAPP(t0, kpA0[1]), TAPP(t1, kp[1][1])), TAPP(t2, kp[2][1]));
        BB = badd(badd(TAPP(t1, kp[0][0]), TAPP(t2, kp[1][0])), TAPP(t3, kp[2][0]));
        AB = badd(badd(TAPP(t1, kp[0][1]), TAPP(t2, kp[1][1])), TAPP(t3, kp[2][1]));
        BC = badd(badd(TAPP(t2, kp[0][0]), TAPP(t3, kp[1][0])), TAPP(t4, kp[2][0]));
        AC = badd(badd(TAPP(t2, kp[0][1]), TAPP(t3, kp[1][1])), TAPP(t4, kp[2][1]));
        BD = badd(badd(TAPP(t3, kp[0][0]), TAPP(t4, kp[1][0])), TAPP(t5, kpD2[0]));
        AD = badd(badd(TAPP(t3, kp[0][1]), TAPP(t4, kp[1][1])), TAPP(t5, kpD2[1]));
    }

    // ---- branchless main loop: load col c, store col c-1 (4 rows) ----
#pragma unroll 2
    for (int c = cbeg + 1; c <= cend; ++c) {
        const size_t cc = (size_t)c * CC;
        const uint32_t t0 = pack2(r0 + cc);
        const uint32_t t1 = pack2(r1 + cc);
        const uint32_t t2 = pack2(r1 + cc + RS);
        const uint32_t t3 = pack2(r1 + cc + 2 * RS);
        const uint32_t t4 = pack2(r1 + cc + 3 * RS);
        const uint32_t t5 = pack2(r5 + cc);

        const size_t po = (size_t)(c - 1) * CC;

        // Row A (h0): t0,t1,t2 (top tap may be zeroed)
        {
            const uint32_t q0 = badd(badd(TAPP(t0, kpA0[0]), TAPP(t1, kp[1][0])), TAPP(t2, kp[2][0]));
            const uint32_t q1 = badd(badd(TAPP(t0, kpA0[1]), TAPP(t1, kp[1][1])), TAPP(t2, kp[2][1]));
            const uint32_t q2 = badd(badd(TAPP(t0, kpA0[2]), TAPP(t1, kp[1][2])), TAPP(t2, kp[2][2]));
            store2(oA + po, badd(AA, q2));
            AA = badd(BA, q1); BA = q0;
        }
        // Row B (h0+1): t1,t2,t3
        {
            const uint32_t q0 = badd(badd(TAPP(t1, kp[0][0]), TAPP(t2, kp[1][0])), TAPP(t3, kp[2][0]));
            const uint32_t q1 = badd(badd(TAPP(t1, kp[0][1]), TAPP(t2, kp[1][1])), TAPP(t3, kp[2][1]));
            const uint32_t q2 = badd(badd(TAPP(t1, kp[0][2]), TAPP(t2, kp[1][2])), TAPP(t3, kp[2][2]));
            store2(oA + po + RS, badd(AB, q2));
            AB = badd(BB, q1); BB = q0;
        }
        // Row C (h0+2): t2,t3,t4
        {
            const uint32_t q0 = badd(badd(TAPP(t2, kp[0][0]), TAPP(t3, kp[1][0])), TAPP(t4, kp[2][0]));
            const uint32_t q1 = badd(badd(TAPP(t2, kp[0][1]), TAPP(t3, kp[1][1])), TAPP(t4, kp[2][1]));
            const uint32_t q2 = badd(badd(TAPP(t2, kp[0][2]), TAPP(t3, kp[1][2])), TAPP(t4, kp[2][2]));
            store2(oA + po + 2 * RS, badd(AC, q2));
            AC = badd(BC, q1); BC = q0;
        }
        // Row D (h0+3): t3,t4,t5 (bottom tap may be zeroed)
        {
            const uint32_t q0 = badd(badd(TAPP(t3, kp[0][0]), TAPP(t4, kp[1][0])), TAPP(t5, kpD2[0]));
            const uint32_t q1 = badd(badd(TAPP(t3, kp[0][1]), TAPP(t4, kp[1][1])), TAPP(t5, kpD2[1]));
            const uint32_t q2 = badd(badd(TAPP(t3, kp[0][2]), TAPP(t4, kp[1][2])), TAPP(t5, kpD2[2]));
            store2(oA + po + 3 * RS, badd(AD, q2));
            AD = badd(BD, q1); BD = q0;
        }
    }

    if (we == WW) {  // right border: out[111] = q0(110) + q1(111) = A
        const size_t po = (size_t)(WW - 1) * CC;
        store2(oA + po,          AA);
        store2(oA + po + RS,     AB);
        store2(oA + po + 2 * RS, AC);
        store2(oA + po + 3 * RS, AD);
    }
}

extern "C" void kernel_launch(void* const* d_in, const int* in_sizes, int n_in,
                              void* d_out, int out_size) {
    const float* x = (const float*)d_in[0];
    const float* k = (const float*)d_in[1];
    float* out = (float*)d_out;
    dim3 grid(112, NN);   // 112 = 28 quads x 4 strips
    bconv_kernel<<<grid, 128>>>(x, k, out);
}